// round 2
// baseline (speedup 1.0000x reference)
#include <cuda_runtime.h>
#include <cstdint>

// ---------------------------------------------------------------------------
// Shapes (fixed): B=16, C=256, W=H=64, K=8, HEADS=8
//   -> aW=aH=8, nP=64, p=64, d=32, BH=128; GEMM row-view [M=65536, 256]
// ---------------------------------------------------------------------------

#define NELEM 16777216   // 16*256*64*64 == 65536*256 == 128*64*64*32

__device__ float g_xu[NELEM];
__device__ float g_q[NELEM];
__device__ float g_k[NELEM];
__device__ float g_v[NELEM];
__device__ float g_attn[NELEM];   // oi, then reused for orr
__device__ float g_proj[NELEM];   // projection output (pre-LN)
__device__ float g_cat[2*NELEM];  // concat(inside, region)  [16,512,64,64]
__device__ float g_c1[NELEM];     // conv1 output

__device__ __forceinline__ float sigm(float v) { return 1.0f / (1.0f + __expf(-v)); }

// ---------------------------------------------------------------------------
// 1) unfold: x[b,c,w,h] -> xu[((b*64+n)*64+pp), c], n=aw*8+ah, pp=kw*8+kh
// ---------------------------------------------------------------------------
__global__ __launch_bounds__(256) void k_unfold(const float* __restrict__ x) {
    int tid = blockIdx.x * 256 + threadIdx.x;        // NCHW linear, h innermost
    int h = tid & 63;
    int w = (tid >> 6) & 63;
    int c = (tid >> 12) & 255;
    int b = tid >> 20;
    int n  = ((w >> 3) << 3) | (h >> 3);
    int pp = ((w & 7) << 3) | (h & 7);
    int row = ((b << 6) | n) * 64 + pp;
    g_xu[(size_t)row * 256 + c] = x[tid];
}

// ---------------------------------------------------------------------------
// 2a) Fused QKV SGEMM: {q,k,v}[M,256] = xu[M,256] @ W{q,k,v}[256,256]^T
//     BM=128 BN=64 BK=16, 256 threads, 8x4 microtile x 3 outputs.
//     A tile loaded once per k-step, shared by all three.
// ---------------------------------------------------------------------------
__global__ __launch_bounds__(256) void k_gemm_qkv(const float* __restrict__ Wq,
                                                  const float* __restrict__ Wk,
                                                  const float* __restrict__ Wv) {
    __shared__ __align__(16) float As[16][128];
    __shared__ __align__(16) float Bs[3][16][64];
    int m0 = blockIdx.x * 128;
    int n0 = blockIdx.y * 64;
    int t  = threadIdx.x;
    int tx = t & 15, ty = t >> 4;

    float acc[3][8][4];
#pragma unroll
    for (int s = 0; s < 3; s++)
#pragma unroll
        for (int i = 0; i < 8; i++)
#pragma unroll
            for (int j = 0; j < 4; j++) acc[s][i][j] = 0.f;

    const float* Ws[3] = {Wq, Wk, Wv};

    for (int k0 = 0; k0 < 256; k0 += 16) {
#pragma unroll
        for (int l = 0; l < 2; l++) {
            int id  = t + l * 256;
            int row = id >> 2, kg = id & 3;
            float4 v = *(const float4*)(g_xu + (size_t)(m0 + row) * 256 + k0 + kg * 4);
            As[kg * 4 + 0][row] = v.x;
            As[kg * 4 + 1][row] = v.y;
            As[kg * 4 + 2][row] = v.z;
            As[kg * 4 + 3][row] = v.w;
        }
        {
            int row = t >> 2, kg = t & 3;
#pragma unroll
            for (int s = 0; s < 3; s++) {
                float4 v = *(const float4*)(Ws[s] + (size_t)(n0 + row) * 256 + k0 + kg * 4);
                Bs[s][kg * 4 + 0][row] = v.x;
                Bs[s][kg * 4 + 1][row] = v.y;
                Bs[s][kg * 4 + 2][row] = v.z;
                Bs[s][kg * 4 + 3][row] = v.w;
            }
        }
        __syncthreads();
#pragma unroll
        for (int kk = 0; kk < 16; kk++) {
            float4 a0 = *(const float4*)&As[kk][ty * 8];
            float4 a1 = *(const float4*)&As[kk][ty * 8 + 4];
            float ar[8] = {a0.x, a0.y, a0.z, a0.w, a1.x, a1.y, a1.z, a1.w};
#pragma unroll
            for (int s = 0; s < 3; s++) {
                float4 b0 = *(const float4*)&Bs[s][kk][tx * 4];
                float br[4] = {b0.x, b0.y, b0.z, b0.w};
#pragma unroll
                for (int i = 0; i < 8; i++)
#pragma unroll
                    for (int j = 0; j < 4; j++) acc[s][i][j] += ar[i] * br[j];
            }
        }
        __syncthreads();
    }

    float* Outs[3] = {g_q, g_k, g_v};
#pragma unroll
    for (int s = 0; s < 3; s++) {
#pragma unroll
        for (int i = 0; i < 8; i++) {
            int m = m0 + ty * 8 + i;
            float4 o;
            o.x = acc[s][i][0];
            o.y = acc[s][i][1];
            o.z = acc[s][i][2];
            o.w = acc[s][i][3];
            *(float4*)(Outs[s] + (size_t)m * 256 + n0 + tx * 4) = o;
        }
    }
}

// ---------------------------------------------------------------------------
// 2b) projection SGEMM: g_proj[M,256] = g_attn[M,256] @ W[256,256]^T + bias
// ---------------------------------------------------------------------------
__global__ __launch_bounds__(256) void k_gemm_proj(const float* __restrict__ Wt,
                                                   const float* __restrict__ bias) {
    __shared__ __align__(16) float As[16][128];
    __shared__ __align__(16) float Bs[16][64];
    int m0 = blockIdx.x * 128;
    int n0 = blockIdx.y * 64;
    int t  = threadIdx.x;
    int tx = t & 15, ty = t >> 4;

    float acc[8][4];
#pragma unroll
    for (int i = 0; i < 8; i++)
#pragma unroll
        for (int j = 0; j < 4; j++) acc[i][j] = 0.f;

    for (int k0 = 0; k0 < 256; k0 += 16) {
#pragma unroll
        for (int l = 0; l < 2; l++) {
            int id  = t + l * 256;
            int row = id >> 2, kg = id & 3;
            float4 v = *(const float4*)(g_attn + (size_t)(m0 + row) * 256 + k0 + kg * 4);
            As[kg * 4 + 0][row] = v.x;
            As[kg * 4 + 1][row] = v.y;
            As[kg * 4 + 2][row] = v.z;
            As[kg * 4 + 3][row] = v.w;
        }
        {
            int row = t >> 2, kg = t & 3;
            float4 v = *(const float4*)(Wt + (size_t)(n0 + row) * 256 + k0 + kg * 4);
            Bs[kg * 4 + 0][row] = v.x;
            Bs[kg * 4 + 1][row] = v.y;
            Bs[kg * 4 + 2][row] = v.z;
            Bs[kg * 4 + 3][row] = v.w;
        }
        __syncthreads();
#pragma unroll
        for (int kk = 0; kk < 16; kk++) {
            float4 a0 = *(const float4*)&As[kk][ty * 8];
            float4 a1 = *(const float4*)&As[kk][ty * 8 + 4];
            float4 b0 = *(const float4*)&Bs[kk][tx * 4];
            float ar[8] = {a0.x, a0.y, a0.z, a0.w, a1.x, a1.y, a1.z, a1.w};
            float br[4] = {b0.x, b0.y, b0.z, b0.w};
#pragma unroll
            for (int i = 0; i < 8; i++)
#pragma unroll
                for (int j = 0; j < 4; j++) acc[i][j] += ar[i] * br[j];
        }
        __syncthreads();
    }

    float bv[4];
#pragma unroll
    for (int j = 0; j < 4; j++) bv[j] = bias[n0 + tx * 4 + j];
#pragma unroll
    for (int i = 0; i < 8; i++) {
        int m = m0 + ty * 8 + i;
        float4 o;
        o.x = acc[i][0] + bv[0];
        o.y = acc[i][1] + bv[1];
        o.z = acc[i][2] + bv[2];
        o.w = acc[i][3] + bv[3];
        *(float4*)(g_proj + (size_t)m * 256 + n0 + tx * 4) = o;
    }
}

// ---------------------------------------------------------------------------
// 3) attention (both stages). Q/K/V viewed as [BH=128, 64, 64, 32].
//    intra (CROSS=false): block=(bh,n), tiles contiguous at blk*2048.
//    cross (CROSS=true) : block=(bh,pp), rows strided by 2048; output
//                         orr[bh,pp,n,d] contiguous at blk*2048.
//    scale (32^-0.5) applied to Q on load (matches ref: qi pre-scaled).
// ---------------------------------------------------------------------------
template <bool CROSS>
__global__ __launch_bounds__(256) void k_attn() {
    __shared__ float Qs[64][33];   // padded; reused for output staging
    __shared__ float Ks[64][32];
    __shared__ float Vs[64][32];
    __shared__ float Ss[64][65];

    const float scale = 0.17677669529663687f;
    int blk = blockIdx.x;
    int t   = threadIdx.x;
    size_t obase = (size_t)blk * 2048;

    if (!CROSS) {
        for (int idx = t; idx < 2048; idx += 256) {
            int r = idx >> 5, d = idx & 31;
            size_t a = obase + idx;
            Qs[r][d] = g_q[a] * scale;
            Ks[r][d] = g_k[a];
            Vs[r][d] = g_v[a];
        }
    } else {
        int bh = blk >> 6, pp = blk & 63;
        size_t qb = (size_t)bh * 131072 + (size_t)pp * 32;
        for (int idx = t; idx < 2048; idx += 256) {
            int r = idx >> 5, d = idx & 31;
            size_t a = qb + (size_t)r * 2048 + d;
            Qs[r][d] = g_q[a] * scale;
            Ks[r][d] = g_k[a];
            Vs[r][d] = g_v[a];
        }
    }
    __syncthreads();

    int i  = t & 63;
    int j0 = (t >> 6) * 16;
    {
        float acc[16];
#pragma unroll
        for (int jj = 0; jj < 16; jj++) acc[jj] = 0.f;
        for (int d = 0; d < 32; d++) {
            float qv = Qs[i][d];
#pragma unroll
            for (int jj = 0; jj < 16; jj++) acc[jj] += qv * Ks[j0 + jj][d];
        }
#pragma unroll
        for (int jj = 0; jj < 16; jj++) Ss[i][j0 + jj] = acc[jj];
    }
    __syncthreads();

    {   // softmax rows: 4 lanes per row
        int r = t >> 2, q = t & 3;
        float mx = -1e30f;
        float ev[16];
#pragma unroll
        for (int c = 0; c < 16; c++) mx = fmaxf(mx, Ss[r][q * 16 + c]);
        mx = fmaxf(mx, __shfl_xor_sync(0xffffffffu, mx, 1));
        mx = fmaxf(mx, __shfl_xor_sync(0xffffffffu, mx, 2));
        float sum = 0.f;
#pragma unroll
        for (int c = 0; c < 16; c++) {
            ev[c] = __expf(Ss[r][q * 16 + c] - mx);
            sum += ev[c];
        }
        sum += __shfl_xor_sync(0xffffffffu, sum, 1);
        sum += __shfl_xor_sync(0xffffffffu, sum, 2);
        float inv = 1.0f / sum;
#pragma unroll
        for (int c = 0; c < 16; c++) Ss[r][q * 16 + c] = ev[c] * inv;
    }
    __syncthreads();

    {   // O = P @ V
        int d0 = (t >> 6) * 8;
        float oacc[8];
#pragma unroll
        for (int dd = 0; dd < 8; dd++) oacc[dd] = 0.f;
        for (int j = 0; j < 64; j++) {
            float p = Ss[i][j];
#pragma unroll
            for (int dd = 0; dd < 8; dd++) oacc[dd] += p * Vs[j][d0 + dd];
        }
#pragma unroll
        for (int dd = 0; dd < 8; dd++) Qs[i][d0 + dd] = oacc[dd];
    }
    __syncthreads();
    for (int idx = t; idx < 2048; idx += 256) {
        int r = idx >> 5, d = idx & 31;
        g_attn[obase + idx] = Qs[r][d];
    }
}

// ---------------------------------------------------------------------------
// 4a) Fused LN + sigmoid-gate + fold, INSIDE branch.
//     Block = (b, n, half): 32 LN rows (pp in [half*32, half*32+32)) staged
//     in smem; outputs cat[:,0:256] with coalesced x reads / cat writes.
// ---------------------------------------------------------------------------
__global__ __launch_bounds__(256) void k_ln_gate_inside(const float* __restrict__ x,
                                                        const float* __restrict__ lg,
                                                        const float* __restrict__ lb) {
    __shared__ float s[32][257];
    __shared__ float m_s[32], i_s[32];

    int blk  = blockIdx.x;
    int half = blk & 1;
    int n    = (blk >> 1) & 63;
    int b    = blk >> 7;
    int t    = threadIdx.x;
    int pp0  = half * 32;

    size_t base = ((size_t)((b * 64 + n) * 64 + pp0)) * 256;
#pragma unroll
    for (int i = 0; i < 32; i++) {
        int idx = t + i * 256;
        s[idx >> 8][idx & 255] = g_proj[base + idx];
    }
    __syncthreads();

    {   // per-row stats: 8 threads/row, cols strided by 8
        int row = t >> 3, q = t & 7;
        float sum = 0.f, sum2 = 0.f;
#pragma unroll
        for (int i = 0; i < 32; i++) {
            float v = s[row][q + 8 * i];
            sum += v; sum2 += v * v;
        }
#pragma unroll
        for (int o = 1; o < 8; o <<= 1) {
            sum  += __shfl_xor_sync(0xffffffffu, sum, o);
            sum2 += __shfl_xor_sync(0xffffffffu, sum2, o);
        }
        if (q == 0) {
            float mean = sum * (1.0f / 256.0f);
            float var  = sum2 * (1.0f / 256.0f) - mean * mean;
            m_s[row] = mean;
            i_s[row] = rsqrtf(var + 1e-5f);
        }
    }
    __syncthreads();

    int h3  = t & 7;
    int wl  = (t >> 3) & 3;
    int cq8 = t >> 5;
    int row = wl * 8 + h3;                 // pp - pp0
    int w   = ((n >> 3) << 3) + half * 4 + wl;
    int h   = ((n & 7) << 3) + h3;
    float mean = m_s[row], inv = i_s[row];
    size_t pix = ((size_t)w << 6) | h;
#pragma unroll
    for (int c0 = 0; c0 < 256; c0 += 8) {
        int c = c0 + cq8;
        float v = (s[row][c] - mean) * inv * lg[c] + lb[c];
        float xv = x[(((size_t)(b * 256 + c)) << 12) + pix];
        g_cat[(((size_t)(b * 512 + c)) << 12) + pix] = xv * sigm(v);
    }
}

// ---------------------------------------------------------------------------
// 4b) Fused LN + sigmoid-gate + fold, REGION branch.
//     LN row = (b, pp2, n2) over c2; output channel cf = pp2*4 + (c2>>6),
//     pix = c2&63, w = (n2>>3)*8 + (pix>>3), h = (n2&7)*8 + (pix&7).
//     Block = (b, pp2, half): n2 in [half*32, half*32+32).
// ---------------------------------------------------------------------------
__global__ __launch_bounds__(256) void k_ln_gate_region(const float* __restrict__ x,
                                                        const float* __restrict__ lg,
                                                        const float* __restrict__ lb) {
    __shared__ float s[32][264];
    __shared__ float m_s[32], i_s[32];

    int blk  = blockIdx.x;
    int half = blk & 1;
    int pp2  = (blk >> 1) & 63;
    int b    = blk >> 7;
    int t    = threadIdx.x;
    int n2_0 = half * 32;

    size_t base = ((size_t)((b * 64 + pp2) * 64 + n2_0)) * 256;
#pragma unroll
    for (int i = 0; i < 32; i++) {
        int idx = t + i * 256;
        s[idx >> 8][idx & 255] = g_proj[base + idx];
    }
    __syncthreads();

    {
        int row = t >> 3, q = t & 7;
        float sum = 0.f, sum2 = 0.f;
#pragma unroll
        for (int i = 0; i < 32; i++) {
            float v = s[row][q + 8 * i];
            sum += v; sum2 += v * v;
        }
#pragma unroll
        for (int o = 1; o < 8; o <<= 1) {
            sum  += __shfl_xor_sync(0xffffffffu, sum, o);
            sum2 += __shfl_xor_sync(0xffffffffu, sum2, o);
        }
        if (q == 0) {
            float mean = sum * (1.0f / 256.0f);
            float var  = sum2 * (1.0f / 256.0f) - mean * mean;
            m_s[row] = mean;
            i_s[row] = rsqrtf(var + 1e-5f);
        }
    }
    __syncthreads();

    int ph = t & 7;
    int nl = (t >> 3) & 7;
    int pl_hi = t >> 6;                    // 0..3 (low 2 bits of pl)
#pragma unroll
    for (int it = 0; it < 32; it++) {
        int cq  = it & 3;
        int nh  = (it >> 2) & 3;
        int ph2 = it >> 4;                 // high bit of pl
        int pl  = ph2 * 4 + pl_hi;
        int row = nh * 8 + nl;             // n2 - n2_0
        int c2  = cq * 64 + pl * 8 + ph;
        int cf  = pp2 * 4 + cq;
        int w   = (half * 4 + nh) * 8 + pl;
        int h   = nl * 8 + ph;
        float v = (s[row][c2] - m_s[row]) * i_s[row] * lg[c2] + lb[c2];
        size_t pix = ((size_t)w << 6) | h;
        float xv = x[(((size_t)(b * 256 + cf)) << 12) + pix];
        g_cat[(((size_t)(b * 512 + 256 + cf)) << 12) + pix] = xv * sigm(v);
    }
}

// ---------------------------------------------------------------------------
// 5) direct 3x3 conv (SAME, pad 1) + bias + eval-BN + ReLU.
//    Block: 64 couts x 16x16 pixels; thread: 8 couts x 8 pixels; cin chunk 8.
//    SRC=0: in=g_cat, out=g_c1.  SRC=1: in=g_c1, out=arg pointer.
// ---------------------------------------------------------------------------
template <int CIN, int SRC>
__global__ __launch_bounds__(256) void k_conv3x3(const float* __restrict__ wgt,
                                                 const float* __restrict__ cb,
                                                 const float* __restrict__ bng,
                                                 const float* __restrict__ bnb,
                                                 const float* __restrict__ bnm,
                                                 const float* __restrict__ bnv,
                                                 float* __restrict__ out_arg) {
    constexpr int CC = 8;
    __shared__ float in_s[CC][18][19];
    __shared__ float w_s[64 * CC * 9];

    const float* in = (SRC == 0) ? g_cat : g_c1;
    float* out = (SRC == 0) ? g_c1 : out_arg;

    int b   = blockIdx.z;
    int co0 = blockIdx.y * 64;
    int tY  = (blockIdx.x >> 2) * 16;
    int tX  = (blockIdx.x & 3) * 16;
    int t   = threadIdx.x;
    int cg  = t >> 5;
    int pg  = t & 31;
    int py  = pg >> 1;
    int px0 = (pg & 1) * 8;

    float acc[8][8];
#pragma unroll
    for (int o = 0; o < 8; o++)
#pragma unroll
        for (int i = 0; i < 8; i++) acc[o][i] = 0.f;

    const float* inb = in + (size_t)b * CIN * 4096;

    for (int ci0 = 0; ci0 < CIN; ci0 += CC) {
        for (int idx = t; idx < CC * 18 * 18; idx += 256) {
            int ci = idx / 324;
            int r  = idx % 324;
            int yy = r / 18, xx = r % 18;
            int gy = tY + yy - 1, gx = tX + xx - 1;
            float v = 0.f;
            if (gy >= 0 && gy < 64 && gx >= 0 && gx < 64)
                v = inb[(size_t)(ci0 + ci) * 4096 + gy * 64 + gx];
            in_s[ci][yy][xx] = v;
        }
        for (int idx = t; idx < 64 * CC * 9; idx += 256) {
            int co = idx / (CC * 9);
            int r  = idx - co * (CC * 9);
            w_s[idx] = wgt[((size_t)(co0 + co) * CIN + ci0) * 9 + r];
        }
        __syncthreads();

#pragma unroll
        for (int ci = 0; ci < CC; ci++) {
#pragma unroll
            for (int ky = 0; ky < 3; ky++) {
#pragma unroll
                for (int kx = 0; kx < 3; kx++) {
                    float wv[8];
#pragma unroll
                    for (int o = 0; o < 8; o++)
                        wv[o] = w_s[((cg * 8 + o) * CC + ci) * 9 + ky * 3 + kx];
                    float iv[8];
#pragma unroll
                    for (int i = 0; i < 8; i++)
                        iv[i] = in_s[ci][py + ky][px0 + kx + i];
#pragma unroll
                    for (int o = 0; o < 8; o++)
#pragma unroll
                        for (int i = 0; i < 8; i++)
                            acc[o][i] += wv[o] * iv[i];
                }
            }
        }
        __syncthreads();
    }

#pragma unroll
    for (int o = 0; o < 8; o++) {
        int co = co0 + cg * 8 + o;
        float sc = bng[co] * rsqrtf(bnv[co] + 1e-5f);
        float sh = (cb[co] - bnm[co]) * sc + bnb[co];
        float4 o0, o1;
        o0.x = fmaxf(acc[o][0] * sc + sh, 0.f);
        o0.y = fmaxf(acc[o][1] * sc + sh, 0.f);
        o0.z = fmaxf(acc[o][2] * sc + sh, 0.f);
        o0.w = fmaxf(acc[o][3] * sc + sh, 0.f);
        o1.x = fmaxf(acc[o][4] * sc + sh, 0.f);
        o1.y = fmaxf(acc[o][5] * sc + sh, 0.f);
        o1.z = fmaxf(acc[o][6] * sc + sh, 0.f);
        o1.w = fmaxf(acc[o][7] * sc + sh, 0.f);
        float* op = out + ((size_t)(b * 256 + co) << 12) + (tY + py) * 64 + tX + px0;
        *(float4*)(op)     = o0;
        *(float4*)(op + 4) = o1;
    }
}

// ---------------------------------------------------------------------------
// launch: kernel launches ONLY (no CUDA API calls -> trivially capturable)
// ---------------------------------------------------------------------------
extern "C" void kernel_launch(void* const* d_in, const int* in_sizes, int n_in,
                              void* d_out, int out_size) {
    (void)in_sizes; (void)n_in; (void)out_size;
    const float* x     = (const float*)d_in[0];
    const float* Wq    = (const float*)d_in[1];
    const float* Wk    = (const float*)d_in[2];
    const float* Wv    = (const float*)d_in[3];
    const float* Wpi   = (const float*)d_in[4];
    const float* bpi   = (const float*)d_in[5];
    const float* lni_g = (const float*)d_in[6];
    const float* lni_b = (const float*)d_in[7];
    const float* Wpr   = (const float*)d_in[8];
    const float* bpr   = (const float*)d_in[9];
    const float* lnr_g = (const float*)d_in[10];
    const float* lnr_b = (const float*)d_in[11];
    const float* cw1   = (const float*)d_in[12];
    const float* cb1   = (const float*)d_in[13];
    const float* bn1_g = (const float*)d_in[14];
    const float* bn1_b = (const float*)d_in[15];
    const float* bn1_m = (const float*)d_in[16];
    const float* bn1_v = (const float*)d_in[17];
    const float* cw2   = (const float*)d_in[18];
    const float* cb2   = (const float*)d_in[19];
    const float* bn2_g = (const float*)d_in[20];
    const float* bn2_b = (const float*)d_in[21];
    const float* bn2_m = (const float*)d_in[22];
    const float* bn2_v = (const float*)d_in[23];
    float* out = (float*)d_out;

    const int NB = NELEM / 256;
    dim3 ggrid(512, 4);

    k_unfold<<<NB, 256>>>(x);
    k_gemm_qkv<<<ggrid, 256>>>(Wq, Wk, Wv);

    k_attn<false><<<8192, 256>>>();
    k_gemm_proj<<<ggrid, 256>>>(Wpi, bpi);
    k_ln_gate_inside<<<2048, 256>>>(x, lni_g, lni_b);

    k_attn<true><<<8192, 256>>>();
    k_gemm_proj<<<ggrid, 256>>>(Wpr, bpr);
    k_ln_gate_region<<<2048, 256>>>(x, lnr_g, lnr_b);

    k_conv3x3<512, 0><<<dim3(16, 4, 16), 256>>>(cw1, cb1, bn1_g, bn1_b, bn1_m, bn1_v, nullptr);
    k_conv3x3<256, 1><<<dim3(16, 4, 16), 256>>>(cw2, cb2, bn2_g, bn2_b, bn2_m, bn2_v, out);
}

// round 8
// speedup vs baseline: 2.1786x; 2.1786x over previous
#include <cuda_runtime.h>
#include <cuda_bf16.h>
#include <cstdint>

// ---------------------------------------------------------------------------
// Shapes (fixed): B=16, C=256, W=H=64, K=8, HEADS=8
//   -> aW=aH=8, nP=64, p=64, d=32, BH=128; GEMM row-view [M=65536, 256]
// R8 = resubmission of R6/R7 (both died on container acquisition; infra
// flake — same error hit the EMPTY R0 stub). tcgen05 is not available
// (.target sm_100, no "a"): convs use warp-level mma.sync bf16 (sm_80+ PTX)
// with 2-term bf16 error splitting (3 passes, one fp32 accumulator).
// Fragment layouts verified against PTX ISA m16n8k16 mappings; budgets
// re-checked (≈110 regs/thread, 110.6KB dynamic smem, 1 CTA/SM).
// ---------------------------------------------------------------------------

#define NELEM 16777216   // 16*256*64*64 == 65536*256

__device__ float g_xu[NELEM];
__device__ float g_q[NELEM];
__device__ float g_k[NELEM];
__device__ float g_v[NELEM];
__device__ float g_attn[NELEM];
__device__ float g_proj[NELEM];
__device__ float g_cat[2*NELEM];                 // [16,512,64,64] fp32 (gate output)

// NHWC bf16 split buffers for tensor-core convs
__device__ __nv_bfloat16 g_nh1_hi[16*4096*512]; // conv1 input  [b,pix,ci]
__device__ __nv_bfloat16 g_nh1_lo[16*4096*512];
__device__ __nv_bfloat16 g_nh2_hi[16*4096*256]; // conv2 input
__device__ __nv_bfloat16 g_nh2_lo[16*4096*256];
// weight tiles per (tap,kc): [hi 16384][lo 16384], K-major [co 256][ci 64]
__device__ __nv_bfloat16 g_w1s[2*9*8*16384];
__device__ __nv_bfloat16 g_w2s[2*9*4*16384];

__device__ __forceinline__ float sigm(float v) { return 1.0f / (1.0f + __expf(-v)); }
__device__ __forceinline__ uint32_t bfu(__nv_bfloat16 h) { return (uint32_t)__bfloat16_as_ushort(h); }

// m16n8k16 bf16 MMA, fp32 accumulate (base sm_80+ PTX; legal on sm_100)
__device__ __forceinline__ void mma_bf16(float* d, const uint32_t* a, uint32_t b0, uint32_t b1) {
    asm volatile(
        "mma.sync.aligned.m16n8k16.row.col.f32.bf16.bf16.f32 "
        "{%0,%1,%2,%3}, {%4,%5,%6,%7}, {%8,%9}, {%0,%1,%2,%3};"
        : "+f"(d[0]), "+f"(d[1]), "+f"(d[2]), "+f"(d[3])
        : "r"(a[0]), "r"(a[1]), "r"(a[2]), "r"(a[3]), "r"(b0), "r"(b1));
}

// ---------------------------------------------------------------------------
// 1) unfold
// ---------------------------------------------------------------------------
__global__ __launch_bounds__(256) void k_unfold(const float* __restrict__ x) {
    int tid = blockIdx.x * 256 + threadIdx.x;
    int h = tid & 63;
    int w = (tid >> 6) & 63;
    int c = (tid >> 12) & 255;
    int b = tid >> 20;
    int n  = ((w >> 3) << 3) | (h >> 3);
    int pp = ((w & 7) << 3) | (h & 7);
    int row = ((b << 6) | n) * 64 + pp;
    g_xu[(size_t)row * 256 + c] = x[tid];
}

// ---------------------------------------------------------------------------
// 2a) Fused QKV SGEMM
// ---------------------------------------------------------------------------
__global__ __launch_bounds__(256) void k_gemm_qkv(const float* __restrict__ Wq,
                                                  const float* __restrict__ Wk,
                                                  const float* __restrict__ Wv) {
    __shared__ __align__(16) float As[16][128];
    __shared__ __align__(16) float Bs[3][16][64];
    int m0 = blockIdx.x * 128;
    int n0 = blockIdx.y * 64;
    int t  = threadIdx.x;
    int tx = t & 15, ty = t >> 4;

    float acc[3][8][4];
#pragma unroll
    for (int s = 0; s < 3; s++)
#pragma unroll
        for (int i = 0; i < 8; i++)
#pragma unroll
            for (int j = 0; j < 4; j++) acc[s][i][j] = 0.f;

    const float* Ws[3] = {Wq, Wk, Wv};

    for (int k0 = 0; k0 < 256; k0 += 16) {
#pragma unroll
        for (int l = 0; l < 2; l++) {
            int id  = t + l * 256;
            int row = id >> 2, kg = id & 3;
            float4 v = *(const float4*)(g_xu + (size_t)(m0 + row) * 256 + k0 + kg * 4);
            As[kg * 4 + 0][row] = v.x;
            As[kg * 4 + 1][row] = v.y;
            As[kg * 4 + 2][row] = v.z;
            As[kg * 4 + 3][row] = v.w;
        }
        {
            int row = t >> 2, kg = t & 3;
#pragma unroll
            for (int s = 0; s < 3; s++) {
                float4 v = *(const float4*)(Ws[s] + (size_t)(n0 + row) * 256 + k0 + kg * 4);
                Bs[s][kg * 4 + 0][row] = v.x;
                Bs[s][kg * 4 + 1][row] = v.y;
                Bs[s][kg * 4 + 2][row] = v.z;
                Bs[s][kg * 4 + 3][row] = v.w;
            }
        }
        __syncthreads();
#pragma unroll
        for (int kk = 0; kk < 16; kk++) {
            float4 a0 = *(const float4*)&As[kk][ty * 8];
            float4 a1 = *(const float4*)&As[kk][ty * 8 + 4];
            float ar[8] = {a0.x, a0.y, a0.z, a0.w, a1.x, a1.y, a1.z, a1.w};
#pragma unroll
            for (int s = 0; s < 3; s++) {
                float4 b0 = *(const float4*)&Bs[s][kk][tx * 4];
                float br[4] = {b0.x, b0.y, b0.z, b0.w};
#pragma unroll
                for (int i = 0; i < 8; i++)
#pragma unroll
                    for (int j = 0; j < 4; j++) acc[s][i][j] += ar[i] * br[j];
            }
        }
        __syncthreads();
    }

    float* Outs[3] = {g_q, g_k, g_v};
#pragma unroll
    for (int s = 0; s < 3; s++) {
#pragma unroll
        for (int i = 0; i < 8; i++) {
            int m = m0 + ty * 8 + i;
            float4 o;
            o.x = acc[s][i][0];
            o.y = acc[s][i][1];
            o.z = acc[s][i][2];
            o.w = acc[s][i][3];
            *(float4*)(Outs[s] + (size_t)m * 256 + n0 + tx * 4) = o;
        }
    }
}

// ---------------------------------------------------------------------------
// 2b) projection SGEMM
// ---------------------------------------------------------------------------
__global__ __launch_bounds__(256) void k_gemm_proj(const float* __restrict__ Wt,
                                                   const float* __restrict__ bias) {
    __shared__ __align__(16) float As[16][128];
    __shared__ __align__(16) float Bs[16][64];
    int m0 = blockIdx.x * 128;
    int n0 = blockIdx.y * 64;
    int t  = threadIdx.x;
    int tx = t & 15, ty = t >> 4;

    float acc[8][4];
#pragma unroll
    for (int i = 0; i < 8; i++)
#pragma unroll
        for (int j = 0; j < 4; j++) acc[i][j] = 0.f;

    for (int k0 = 0; k0 < 256; k0 += 16) {
#pragma unroll
        for (int l = 0; l < 2; l++) {
            int id  = t + l * 256;
            int row = id >> 2, kg = id & 3;
            float4 v = *(const float4*)(g_attn + (size_t)(m0 + row) * 256 + k0 + kg * 4);
            As[kg * 4 + 0][row] = v.x;
            As[kg * 4 + 1][row] = v.y;
            As[kg * 4 + 2][row] = v.z;
            As[kg * 4 + 3][row] = v.w;
        }
        {
            int row = t >> 2, kg = t & 3;
            float4 v = *(const float4*)(Wt + (size_t)(n0 + row) * 256 + k0 + kg * 4);
            Bs[kg * 4 + 0][row] = v.x;
            Bs[kg * 4 + 1][row] = v.y;
            Bs[kg * 4 + 2][row] = v.z;
            Bs[kg * 4 + 3][row] = v.w;
        }
        __syncthreads();
#pragma unroll
        for (int kk = 0; kk < 16; kk++) {
            float4 a0 = *(const float4*)&As[kk][ty * 8];
            float4 a1 = *(const float4*)&As[kk][ty * 8 + 4];
            float4 b0 = *(const float4*)&Bs[kk][tx * 4];
            float ar[8] = {a0.x, a0.y, a0.z, a0.w, a1.x, a1.y, a1.z, a1.w};
            float br[4] = {b0.x, b0.y, b0.z, b0.w};
#pragma unroll
            for (int i = 0; i < 8; i++)
#pragma unroll
                for (int j = 0; j < 4; j++) acc[i][j] += ar[i] * br[j];
        }
        __syncthreads();
    }

    float bv[4];
#pragma unroll
    for (int j = 0; j < 4; j++) bv[j] = bias[n0 + tx * 4 + j];
#pragma unroll
    for (int i = 0; i < 8; i++) {
        int m = m0 + ty * 8 + i;
        float4 o;
        o.x = acc[i][0] + bv[0];
        o.y = acc[i][1] + bv[1];
        o.z = acc[i][2] + bv[2];
        o.w = acc[i][3] + bv[3];
        *(float4*)(g_proj + (size_t)m * 256 + n0 + tx * 4) = o;
    }
}

// ---------------------------------------------------------------------------
// 3) attention (both stages)
// ---------------------------------------------------------------------------
template <bool CROSS>
__global__ __launch_bounds__(256) void k_attn() {
    __shared__ float Qs[64][33];
    __shared__ float Ks[64][32];
    __shared__ float Vs[64][32];
    __shared__ float Ss[64][65];

    const float scale = 0.17677669529663687f;
    int blk = blockIdx.x;
    int t   = threadIdx.x;
    size_t obase = (size_t)blk * 2048;

    if (!CROSS) {
        for (int idx = t; idx < 2048; idx += 256) {
            int r = idx >> 5, d = idx & 31;
            size_t a = obase + idx;
            Qs[r][d] = g_q[a] * scale;
            Ks[r][d] = g_k[a];
            Vs[r][d] = g_v[a];
        }
    } else {
        int bh = blk >> 6, pp = blk & 63;
        size_t qb = (size_t)bh * 131072 + (size_t)pp * 32;
        for (int idx = t; idx < 2048; idx += 256) {
            int r = idx >> 5, d = idx & 31;
            size_t a = qb + (size_t)r * 2048 + d;
            Qs[r][d] = g_q[a] * scale;
            Ks[r][d] = g_k[a];
            Vs[r][d] = g_v[a];
        }
    }
    __syncthreads();

    int i  = t & 63;
    int j0 = (t >> 6) * 16;
    {
        float acc[16];
#pragma unroll
        for (int jj = 0; jj < 16; jj++) acc[jj] = 0.f;
        for (int d = 0; d < 32; d++) {
            float qv = Qs[i][d];
#pragma unroll
            for (int jj = 0; jj < 16; jj++) acc[jj] += qv * Ks[j0 + jj][d];
        }
#pragma unroll
        for (int jj = 0; jj < 16; jj++) Ss[i][j0 + jj] = acc[jj];
    }
    __syncthreads();

    {
        int r = t >> 2, q = t & 3;
        float mx = -1e30f;
        float ev[16];
#pragma unroll
        for (int c = 0; c < 16; c++) mx = fmaxf(mx, Ss[r][q * 16 + c]);
        mx = fmaxf(mx, __shfl_xor_sync(0xffffffffu, mx, 1));
        mx = fmaxf(mx, __shfl_xor_sync(0xffffffffu, mx, 2));
        float sum = 0.f;
#pragma unroll
        for (int c = 0; c < 16; c++) {
            ev[c] = __expf(Ss[r][q * 16 + c] - mx);
            sum += ev[c];
        }
        sum += __shfl_xor_sync(0xffffffffu, sum, 1);
        sum += __shfl_xor_sync(0xffffffffu, sum, 2);
        float inv = 1.0f / sum;
#pragma unroll
        for (int c = 0; c < 16; c++) Ss[r][q * 16 + c] = ev[c] * inv;
    }
    __syncthreads();

    {
        int d0 = (t >> 6) * 8;
        float oacc[8];
#pragma unroll
        for (int dd = 0; dd < 8; dd++) oacc[dd] = 0.f;
        for (int j = 0; j < 64; j++) {
            float p = Ss[i][j];
#pragma unroll
            for (int dd = 0; dd < 8; dd++) oacc[dd] += p * Vs[j][d0 + dd];
        }
#pragma unroll
        for (int dd = 0; dd < 8; dd++) Qs[i][d0 + dd] = oacc[dd];
    }
    __syncthreads();
    for (int idx = t; idx < 2048; idx += 256) {
        int r = idx >> 5, d = idx & 31;
        g_attn[obase + idx] = Qs[r][d];
    }
}

// ---------------------------------------------------------------------------
// 4a) Fused LN + sigmoid-gate + fold, INSIDE branch
// ---------------------------------------------------------------------------
__global__ __launch_bounds__(256) void k_ln_gate_inside(const float* __restrict__ x,
                                                        const float* __restrict__ lg,
                                                        const float* __restrict__ lb) {
    __shared__ float s[32][257];
    __shared__ float m_s[32], i_s[32];

    int blk  = blockIdx.x;
    int half = blk & 1;
    int n    = (blk >> 1) & 63;
    int b    = blk >> 7;
    int t    = threadIdx.x;
    int pp0  = half * 32;

    size_t base = ((size_t)((b * 64 + n) * 64 + pp0)) * 256;
#pragma unroll
    for (int i = 0; i < 32; i++) {
        int idx = t + i * 256;
        s[idx >> 8][idx & 255] = g_proj[base + idx];
    }
    __syncthreads();

    {
        int row = t >> 3, q = t & 7;
        float sum = 0.f, sum2 = 0.f;
#pragma unroll
        for (int i = 0; i < 32; i++) {
            float v = s[row][q + 8 * i];
            sum += v; sum2 += v * v;
        }
#pragma unroll
        for (int o = 1; o < 8; o <<= 1) {
            sum  += __shfl_xor_sync(0xffffffffu, sum, o);
            sum2 += __shfl_xor_sync(0xffffffffu, sum2, o);
        }
        if (q == 0) {
            float mean = sum * (1.0f / 256.0f);
            float var  = sum2 * (1.0f / 256.0f) - mean * mean;
            m_s[row] = mean;
            i_s[row] = rsqrtf(var + 1e-5f);
        }
    }
    __syncthreads();

    int h3  = t & 7;
    int wl  = (t >> 3) & 3;
    int cq8 = t >> 5;
    int row = wl * 8 + h3;
    int w   = ((n >> 3) << 3) + half * 4 + wl;
    int h   = ((n & 7) << 3) + h3;
    float mean = m_s[row], inv = i_s[row];
    size_t pix = ((size_t)w << 6) | h;
#pragma unroll
    for (int c0 = 0; c0 < 256; c0 += 8) {
        int c = c0 + cq8;
        float v = (s[row][c] - mean) * inv * lg[c] + lb[c];
        float xv = x[(((size_t)(b * 256 + c)) << 12) + pix];
        g_cat[(((size_t)(b * 512 + c)) << 12) + pix] = xv * sigm(v);
    }
}

// ---------------------------------------------------------------------------
// 4b) Fused LN + sigmoid-gate + fold, REGION branch
// ---------------------------------------------------------------------------
__global__ __launch_bounds__(256) void k_ln_gate_region(const float* __restrict__ x,
                                                        const float* __restrict__ lg,
                                                        const float* __restrict__ lb) {
    __shared__ float s[32][264];
    __shared__ float m_s[32], i_s[32];

    int blk  = blockIdx.x;
    int half = blk & 1;
    int pp2  = (blk >> 1) & 63;
    int b    = blk >> 7;
    int t    = threadIdx.x;
    int n2_0 = half * 32;

    size_t base = ((size_t)((b * 64 + pp2) * 64 + n2_0)) * 256;
#pragma unroll
    for (int i = 0; i < 32; i++) {
        int idx = t + i * 256;
        s[idx >> 8][idx & 255] = g_proj[base + idx];
    }
    __syncthreads();

    {
        int row = t >> 3, q = t & 7;
        float sum = 0.f, sum2 = 0.f;
#pragma unroll
        for (int i = 0; i < 32; i++) {
            float v = s[row][q + 8 * i];
            sum += v; sum2 += v * v;
        }
#pragma unroll
        for (int o = 1; o < 8; o <<= 1) {
            sum  += __shfl_xor_sync(0xffffffffu, sum, o);
            sum2 += __shfl_xor_sync(0xffffffffu, sum2, o);
        }
        if (q == 0) {
            float mean = sum * (1.0f / 256.0f);
            float var  = sum2 * (1.0f / 256.0f) - mean * mean;
            m_s[row] = mean;
            i_s[row] = rsqrtf(var + 1e-5f);
        }
    }
    __syncthreads();

    int ph = t & 7;
    int nl = (t >> 3) & 7;
    int pl_hi = t >> 6;
#pragma unroll
    for (int it = 0; it < 32; it++) {
        int cq  = it & 3;
        int nh  = (it >> 2) & 3;
        int ph2 = it >> 4;
        int pl  = ph2 * 4 + pl_hi;
        int row = nh * 8 + nl;
        int c2  = cq * 64 + pl * 8 + ph;
        int cf  = pp2 * 4 + cq;
        int w   = (half * 4 + nh) * 8 + pl;
        int h   = nl * 8 + ph;
        float v = (s[row][c2] - m_s[row]) * i_s[row] * lg[c2] + lb[c2];
        size_t pix = ((size_t)w << 6) | h;
        float xv = x[(((size_t)(b * 256 + cf)) << 12) + pix];
        g_cat[(((size_t)(b * 512 + 256 + cf)) << 12) + pix] = xv * sigm(v);
    }
}

// ---------------------------------------------------------------------------
// 4c) NCHW fp32 -> NHWC bf16 hi/lo split (conv1 input prep)
// ---------------------------------------------------------------------------
__global__ __launch_bounds__(256) void k_split_nhwc() {
    __shared__ float s[64][65];
    int b  = blockIdx.z;
    int c0 = blockIdx.y * 64;
    int p0 = blockIdx.x * 64;
    int t  = threadIdx.x;
#pragma unroll
    for (int i = 0; i < 16; i++) {
        int idx = i * 256 + t;
        int ch = idx >> 6, px = idx & 63;
        s[ch][px] = g_cat[(((size_t)(b * 512 + c0 + ch)) << 12) + p0 + px];
    }
    __syncthreads();
#pragma unroll
    for (int i = 0; i < 16; i++) {
        int idx = i * 256 + t;
        int px = idx >> 6, ch = idx & 63;
        float v = s[ch][px];
        __nv_bfloat16 hb = __float2bfloat16(v);
        float lv = v - __bfloat162float(hb);
        size_t o = ((size_t)(b * 4096 + p0 + px)) * 512 + c0 + ch;
        g_nh1_hi[o] = hb;
        g_nh1_lo[o] = __float2bfloat16(lv);
    }
}

// ---------------------------------------------------------------------------
// 4d) weight prep: fp32 OIHW -> bf16 hi/lo K-major tiles [co 256][ci 64]
// ---------------------------------------------------------------------------
template <int CIN>
__global__ __launch_bounds__(256) void k_prep_w(const float* __restrict__ w) {
    constexpr int KC = CIN / 64;
    int idx = blockIdx.x * 256 + threadIdx.x;     // ((tap*KC+kc)*256+co)*64+cl
    int cl = idx & 63;
    int co = (idx >> 6) & 255;
    int s  = idx >> 14;                           // tap*KC + kc
    int kc = s % KC;
    int tap = s / KC;
    float v = w[((size_t)co * CIN + kc * 64 + cl) * 9 + tap];
    __nv_bfloat16 hb = __float2bfloat16(v);
    float lv = v - __bfloat162float(hb);
    __nv_bfloat16* dst = (CIN == 512 ? g_w1s : g_w2s) + (size_t)s * 32768;
    dst[co * 64 + cl] = hb;
    dst[16384 + co * 64 + cl] = __float2bfloat16(lv);
}

// ---------------------------------------------------------------------------
// 5) mma.sync implicit-GEMM 3x3 conv + bias + BN + ReLU.
//    512 threads = 16 warps (4m x 4n); block tile 128 px x 256 co;
//    warp tile m32 x n64; K chunk = 64 ci per tap; 3 bf16 passes into one
//    fp32 accumulator. Smem: A hi/lo [128][72], W hi/lo [256][72] (pad 8).
//    CIN=512: in=g_nh1, epilogue -> g_nh2 bf16 hi/lo.
//    CIN=256: in=g_nh2, epilogue -> out NCHW fp32.
// ---------------------------------------------------------------------------
template <int CIN>
__global__ __launch_bounds__(512, 1) void k_conv_mma(const float* __restrict__ cb,
                                                     const float* __restrict__ bng,
                                                     const float* __restrict__ bnb,
                                                     const float* __restrict__ bnm,
                                                     const float* __restrict__ bnv,
                                                     float* __restrict__ out) {
    constexpr int KC = CIN / 64;
    extern __shared__ __align__(16) char dsm[];
    __nv_bfloat16* Ah = (__nv_bfloat16*)dsm;        // [128][72]
    __nv_bfloat16* Al = Ah + 128 * 72;
    __nv_bfloat16* Wh = Al + 128 * 72;              // [256][72]
    __nv_bfloat16* Wl = Wh + 256 * 72;
    __shared__ float s_sc[256], s_sh[256];

    int t    = threadIdx.x;
    int b    = blockIdx.y;
    int p0   = blockIdx.x * 128;
    int lane = t & 31;
    int wid  = t >> 5;
    int wm   = wid & 3;          // warp m index (32 px each)
    int wn   = wid >> 2;         // warp n index (64 co each)
    int g    = lane >> 2;
    int q    = lane & 3;

    if (t < 256) {
        float inv = rsqrtf(bnv[t] + 1e-5f);
        float sc = bng[t] * inv;
        s_sc[t] = sc;
        s_sh[t] = (cb[t] - bnm[t]) * sc + bnb[t];
    }

    float acc[2][8][4];
#pragma unroll
    for (int s = 0; s < 2; s++)
#pragma unroll
        for (int j = 0; j < 8; j++)
#pragma unroll
            for (int r = 0; r < 4; r++) acc[s][j][r] = 0.f;

    const __nv_bfloat16* nin_hi = (CIN == 512) ? g_nh1_hi : g_nh2_hi;
    const __nv_bfloat16* nin_lo = (CIN == 512) ? g_nh1_lo : g_nh2_lo;
    const __nv_bfloat16* wsrc   = (CIN == 512) ? g_w1s : g_w2s;

    const uint32_t* Ah32 = (const uint32_t*)Ah;   // row stride 36 b32
    const uint32_t* Al32 = (const uint32_t*)Al;
    const uint32_t* Wh32 = (const uint32_t*)Wh;
    const uint32_t* Wl32 = (const uint32_t*)Wl;

    int y0 = p0 >> 6;   // two image rows per block

    for (int tap = 0; tap < 9; tap++) {
        int dy = tap / 3 - 1;
        int dx = tap % 3 - 1;
        for (int kc = 0; kc < KC; kc++) {
            // --- stage A hi/lo: 128 rows x 8 x 16B x 2 planes = 2048 uint4 ---
#pragma unroll
            for (int i = 0; i < 4; i++) {
                int idx = t + i * 512;
                int cc  = idx & 7;
                int r   = (idx >> 3) & 127;
                int pl  = idx >> 10;
                int y = y0 + (r >> 6) + dy;
                int x = (r & 63) + dx;
                uint4 val = make_uint4(0, 0, 0, 0);
                if (y >= 0 && y < 64 && x >= 0 && x < 64) {
                    const __nv_bfloat16* src = pl ? nin_lo : nin_hi;
                    val = *(const uint4*)(src + ((size_t)(b * 4096 + y * 64 + x)) * CIN
                                          + kc * 64 + cc * 8);
                }
                __nv_bfloat16* dstp = pl ? Al : Ah;
                *(uint4*)(dstp + r * 72 + cc * 8) = val;
            }
            // --- stage W hi/lo: 256 rows x 8 x 16B x 2 planes = 4096 uint4 ---
            {
                const __nv_bfloat16* wbase = wsrc + (size_t)(tap * KC + kc) * 32768;
#pragma unroll
                for (int i = 0; i < 8; i++) {
                    int idx = t + i * 512;
                    int cc  = idx & 7;
                    int co  = (idx >> 3) & 255;
                    int pl  = idx >> 11;
                    __nv_bfloat16* dstp = pl ? Wl : Wh;
                    *(uint4*)(dstp + co * 72 + cc * 8) =
                        *(const uint4*)(wbase + pl * 16384 + co * 64 + cc * 8);
                }
            }
            __syncthreads();

            // --- compute: 4 ksteps x (2 m-subtiles x 8 n-subtiles) x 3 passes ---
#pragma unroll
            for (int k0 = 0; k0 < 4; k0++) {      // k offset = k0*16 bf16 = k0*8 b32
                uint32_t ah[2][4], al[2][4];
#pragma unroll
                for (int s = 0; s < 2; s++) {
                    int row = wm * 32 + s * 16 + g;
                    int off = row * 36 + k0 * 8 + q;
                    ah[s][0] = Ah32[off];
                    ah[s][1] = Ah32[off + 8 * 36];
                    ah[s][2] = Ah32[off + 4];
                    ah[s][3] = Ah32[off + 8 * 36 + 4];
                    al[s][0] = Al32[off];
                    al[s][1] = Al32[off + 8 * 36];
                    al[s][2] = Al32[off + 4];
                    al[s][3] = Al32[off + 8 * 36 + 4];
                }
#pragma unroll
                for (int j = 0; j < 8; j++) {
                    int woff = (wn * 64 + j * 8 + g) * 36 + k0 * 8 + q;
                    uint32_t wh0 = Wh32[woff], wh1 = Wh32[woff + 4];
                    uint32_t wl0 = Wl32[woff], wl1 = Wl32[woff + 4];
#pragma unroll
                    for (int s = 0; s < 2; s++) {
                        mma_bf16(acc[s][j], ah[s], wh0, wh1);
                        mma_bf16(acc[s][j], ah[s], wl0, wl1);
                        mma_bf16(acc[s][j], al[s], wh0, wh1);
                    }
                }
            }
            __syncthreads();
        }
    }

    // --- epilogue: BN + ReLU; D layout: d0/d1 at (m=g, n=2q/2q+1), d2/d3 at m=g+8 ---
#pragma unroll
    for (int s = 0; s < 2; s++) {
        int m = p0 + wm * 32 + s * 16 + g;
#pragma unroll
        for (int j = 0; j < 8; j++) {
            int n = wn * 64 + j * 8 + 2 * q;
            float v0 = fmaxf(acc[s][j][0] * s_sc[n]     + s_sh[n],     0.f);
            float v1 = fmaxf(acc[s][j][1] * s_sc[n + 1] + s_sh[n + 1], 0.f);
            float v2 = fmaxf(acc[s][j][2] * s_sc[n]     + s_sh[n],     0.f);
            float v3 = fmaxf(acc[s][j][3] * s_sc[n + 1] + s_sh[n + 1], 0.f);
            if (CIN == 512) {
                __nv_bfloat16 h0 = __float2bfloat16(v0), h1 = __float2bfloat16(v1);
                __nv_bfloat16 h2 = __float2bfloat16(v2), h3 = __float2bfloat16(v3);
                __nv_bfloat16 e0 = __float2bfloat16(v0 - __bfloat162float(h0));
                __nv_bfloat16 e1 = __float2bfloat16(v1 - __bfloat162float(h1));
                __nv_bfloat16 e2 = __float2bfloat16(v2 - __bfloat162float(h2));
                __nv_bfloat16 e3 = __float2bfloat16(v3 - __bfloat162float(h3));
                size_t r0 = ((size_t)(b * 4096 + m)) * 256 + n;
                size_t r1 = ((size_t)(b * 4096 + m + 8)) * 256 + n;
                *(uint32_t*)(g_nh2_hi + r0) = bfu(h0) | (bfu(h1) << 16);
                *(uint32_t*)(g_nh2_lo + r0) = bfu(e0) | (bfu(e1) << 16);
                *(uint32_t*)(g_nh2_hi + r1) = bfu(h2) | (bfu(h3) << 16);
                *(uint32_t*)(g_nh2_lo + r1) = bfu(e2) | (bfu(e3) << 16);
            } else {
                out[(((size_t)(b * 256 + n)) << 12) + m]         = v0;
                out[(((size_t)(b * 256 + n + 1)) << 12) + m]     = v1;
                out[(((size_t)(b * 256 + n)) << 12) + m + 8]     = v2;
                out[(((size_t)(b * 256 + n + 1)) << 12) + m + 8] = v3;
            }
        }
    }
}

// ---------------------------------------------------------------------------
// launch
// ---------------------------------------------------------------------------
extern "C" void kernel_launch(void* const* d_in, const int* in_sizes, int n_in,
                              void* d_out, int out_size) {
    (void)in_sizes; (void)n_in; (void)out_size;
    const float* x     = (const float*)d_in[0];
    const float* Wq    = (const float*)d_in[1];
    const float* Wk    = (const float*)d_in[2];
    const float* Wv    = (const float*)d_in[3];
    const float* Wpi   = (const float*)d_in[4];
    const float* bpi   = (const float*)d_in[5];
    const float* lni_g = (const float*)d_in[6];
    const float* lni_b = (const float*)d_in[7];
    const float* Wpr   = (const float*)d_in[8];
    const float* bpr   = (const float*)d_in[9];
    const float* lnr_g = (const float*)d_in[10];
    const float* lnr_b = (const float*)d_in[11];
    const float* cw1   = (const float*)d_in[12];
    const float* cb1   = (const float*)d_in[13];
    const float* bn1_g = (const float*)d_in[14];
    const float* bn1_b = (const float*)d_in[15];
    const float* bn1_m = (const float*)d_in[16];
    const float* bn1_v = (const float*)d_in[17];
    const float* cw2   = (const float*)d_in[18];
    const float* cb2   = (const float*)d_in[19];
    const float* bn2_g = (const float*)d_in[20];
    const float* bn2_b = (const float*)d_in[21];
    const float* bn2_m = (const float*)d_in[22];
    const float* bn2_v = (const float*)d_in[23];
    float* out = (float*)d_out;

    const int NB = NELEM / 256;
    dim3 ggrid(512, 4);
    const int CONV_SMEM = (2 * 128 * 72 + 2 * 256 * 72) * 2;   // 110592 B

    cudaFuncSetAttribute(k_conv_mma<512>, cudaFuncAttributeMaxDynamicSharedMemorySize, CONV_SMEM);
    cudaFuncSetAttribute(k_conv_mma<256>, cudaFuncAttributeMaxDynamicSharedMemorySize, CONV_SMEM);

    // weight prep (independent of data path)
    k_prep_w<512><<<(9 * 8 * 16384) / 256, 256>>>(cw1);
    k_prep_w<256><<<(9 * 4 * 16384) / 256, 256>>>(cw2);

    k_unfold<<<NB, 256>>>(x);
    k_gemm_qkv<<<ggrid, 256>>>(Wq, Wk, Wv);

    k_attn<false><<<8192, 256>>>();
    k_gemm_proj<<<ggrid, 256>>>(Wpi, bpi);
    k_ln_gate_inside<<<2048, 256>>>(x, lni_g, lni_b);

    k_attn<true><<<8192, 256>>>();
    k_gemm_proj<<<ggrid, 256>>>(Wpr, bpr);
    k_ln_gate_region<<<2048, 256>>>(x, lnr_g, lnr_b);

    k_split_nhwc<<<dim3(64, 8, 16), 256>>>();

    k_conv_mma<512><<<dim3(32, 16), 512, CONV_SMEM>>>(cb1, bn1_g, bn1_b, bn1_m, bn1_v, nullptr);
    k_conv_mma<256><<<dim3(32, 16), 512, CONV_SMEM>>>(cb2, bn2_g, bn2_b, bn2_m, bn2_v, out);
}

// round 16
// speedup vs baseline: 2.5161x; 1.1549x over previous
#include <cuda_runtime.h>
#include <cuda_bf16.h>
#include <cstdint>

// ---------------------------------------------------------------------------
// Shapes (fixed): B=16, C=256, W=H=64, K=8, HEADS=8
//   -> aW=aH=8, nP=64, p=64, d=32, BH=128; GEMM row-view [M=65536, 256]
// R16 = byte-identical resubmission of R15 (died on container acquisition;
// recurring infra flake, no signal). R15 fixes the ROOT CAUSE of the 512MB
// guard trips (R9/R12/R14, identical deltas): __device__ symbols passed as
// kernel arguments from HOST code resolve to bogus (host-shadow) addresses;
// with HMM/ATS those accesses silently migrate pages -> device memory
// growth. R8 passed with the same math because all globals were referenced
// inside kernels. Fix: selector ints; globals resolved inside kernels only.
// ---------------------------------------------------------------------------

#define NELEM 16777216   // 16*256*64*64 == 65536*256

__device__ float g_xu[NELEM];
__device__ float g_q[NELEM];
__device__ float g_k[NELEM];
__device__ float g_v[NELEM];
__device__ float g_attn[NELEM];
__device__ float g_proj[NELEM];
__device__ float g_cat[2*NELEM];                 // [16,512,64,64] fp32 (gate output)

// NHWC bf16 split buffers for tensor-core convs
__device__ __nv_bfloat16 g_nh1_hi[16*4096*512]; // conv1 input  [b,pix,ci]
__device__ __nv_bfloat16 g_nh1_lo[16*4096*512];
__device__ __nv_bfloat16 g_nh2_hi[16*4096*256]; // conv2 input
__device__ __nv_bfloat16 g_nh2_lo[16*4096*256];
// conv weight tiles per (tap,kc): [hi 16384][lo 16384], K-major [co][ci 64]
__device__ __nv_bfloat16 g_w1s[2*9*8*16384];
__device__ __nv_bfloat16 g_w2s[2*9*4*16384];

// GEMM operand splits (A reused sequentially for xu/attn1/attn2)
__device__ __nv_bfloat16 g_a_hi[NELEM];         // [M,256] bf16 hi
__device__ __nv_bfloat16 g_a_lo[NELEM];
__device__ __nv_bfloat16 g_gw_hi[5*65536];      // 5 weights [256,256]
__device__ __nv_bfloat16 g_gw_lo[5*65536];

__device__ __forceinline__ float sigm(float v) { return 1.0f / (1.0f + __expf(-v)); }
__device__ __forceinline__ uint32_t bfu(__nv_bfloat16 h) { return (uint32_t)__bfloat16_as_ushort(h); }

// scalar bf16 hi/lo packers
__device__ __forceinline__ uint32_t packh2(float a, float b) {
    return bfu(__float2bfloat16(a)) | (bfu(__float2bfloat16(b)) << 16);
}
__device__ __forceinline__ uint32_t packl2(float a, float b) {
    float la = a - __bfloat162float(__float2bfloat16(a));
    float lb = b - __bfloat162float(__float2bfloat16(b));
    return bfu(__float2bfloat16(la)) | (bfu(__float2bfloat16(lb)) << 16);
}

// m16n8k16 bf16 MMA, fp32 accumulate (base sm_80+ PTX; legal on sm_100)
__device__ __forceinline__ void mma_bf16(float* d, const uint32_t* a, uint32_t b0, uint32_t b1) {
    asm volatile(
        "mma.sync.aligned.m16n8k16.row.col.f32.bf16.bf16.f32 "
        "{%0,%1,%2,%3}, {%4,%5,%6,%7}, {%8,%9}, {%0,%1,%2,%3};"
        : "+f"(d[0]), "+f"(d[1]), "+f"(d[2]), "+f"(d[3])
        : "r"(a[0]), "r"(a[1]), "r"(a[2]), "r"(a[3]), "r"(b0), "r"(b1));
}

// ---------------------------------------------------------------------------
// 1) unfold
// ---------------------------------------------------------------------------
__global__ __launch_bounds__(256) void k_unfold(const float* __restrict__ x) {
    int tid = blockIdx.x * 256 + threadIdx.x;
    int h = tid & 63;
    int w = (tid >> 6) & 63;
    int c = (tid >> 12) & 255;
    int b = tid >> 20;
    int n  = ((w >> 3) << 3) | (h >> 3);
    int pp = ((w & 7) << 3) | (h & 7);
    int row = ((b << 6) | n) * 64 + pp;
    g_xu[(size_t)row * 256 + c] = x[tid];
}

// ---------------------------------------------------------------------------
// 1b) GEMM operand prep: fp32 -> bf16 hi/lo. srcsel: 0=g_xu, 1=g_attn.
// ---------------------------------------------------------------------------
__global__ __launch_bounds__(256) void k_split_a(int srcsel) {
    const float* src = srcsel ? g_attn : g_xu;
    int idx = (blockIdx.x * 256 + threadIdx.x) * 4;
    float4 f = *(const float4*)(src + idx);
    *(uint2*)(g_a_hi + idx) = make_uint2(packh2(f.x, f.y), packh2(f.z, f.w));
    *(uint2*)(g_a_lo + idx) = make_uint2(packl2(f.x, f.y), packl2(f.z, f.w));
}

__global__ __launch_bounds__(256) void k_split_w(const float* __restrict__ src, int widx) {
    int idx = (blockIdx.x * 256 + threadIdx.x) * 4;
    float4 f = *(const float4*)(src + idx);
    size_t o = (size_t)widx * 65536 + idx;
    *(uint2*)(g_gw_hi + o) = make_uint2(packh2(f.x, f.y), packh2(f.z, f.w));
    *(uint2*)(g_gw_lo + o) = make_uint2(packl2(f.x, f.y), packl2(f.z, f.w));
}

// ---------------------------------------------------------------------------
// 2) mma.sync GEMM: C[M,256] = A[M,256] @ W[256,256]^T (+bias).
//    A = g_a_hi/lo (pre-split); W selected by widx; OUTPUT selected by
//    outsel inside the kernel (0=g_q,1=g_k,2=g_v,3=g_proj).
//    512 threads = 16 warps (4m x 4n); block 128 rows x 256 cols.
// ---------------------------------------------------------------------------
template <int HAS_BIAS>
__global__ __launch_bounds__(512, 1) void k_gemm_mma(int widx, int outsel,
                                                     const float* __restrict__ bias) {
    extern __shared__ __align__(16) char dsm[];
    __nv_bfloat16* Ah = (__nv_bfloat16*)dsm;        // [128][72]
    __nv_bfloat16* Al = Ah + 128 * 72;
    __nv_bfloat16* Wh = Al + 128 * 72;              // [256][72]
    __nv_bfloat16* Wl = Wh + 256 * 72;
    __shared__ float s_b[256];

    float* C = (outsel == 0) ? g_q : (outsel == 1) ? g_k : (outsel == 2) ? g_v : g_proj;

    int t    = threadIdx.x;
    int m0   = blockIdx.x * 128;
    int lane = t & 31;
    int wid  = t >> 5;
    int wm   = wid & 3;
    int wn   = wid >> 2;
    int g    = lane >> 2;
    int q    = lane & 3;

    if (t < 256) s_b[t] = HAS_BIAS ? bias[t] : 0.f;

    float acc[2][8][4];
#pragma unroll
    for (int s = 0; s < 2; s++)
#pragma unroll
        for (int j = 0; j < 8; j++)
#pragma unroll
            for (int r = 0; r < 4; r++) acc[s][j][r] = 0.f;

    const __nv_bfloat16* wbh = g_gw_hi + (size_t)widx * 65536;
    const __nv_bfloat16* wbl = g_gw_lo + (size_t)widx * 65536;

    const uint32_t* Ah32 = (const uint32_t*)Ah;
    const uint32_t* Al32 = (const uint32_t*)Al;
    const uint32_t* Wh32 = (const uint32_t*)Wh;
    const uint32_t* Wl32 = (const uint32_t*)Wl;

    for (int kc = 0; kc < 4; kc++) {
        // stage A: 128 rows x 8 x 16B x 2 planes = 2048 uint4 (plain copies)
#pragma unroll
        for (int i = 0; i < 4; i++) {
            int idx = t + i * 512;
            int cc  = idx & 7;
            int r   = (idx >> 3) & 127;
            int pl  = idx >> 10;
            const __nv_bfloat16* src = pl ? g_a_lo : g_a_hi;
            __nv_bfloat16* dstp = pl ? Al : Ah;
            *(uint4*)(dstp + r * 72 + cc * 8) =
                *(const uint4*)(src + (size_t)(m0 + r) * 256 + kc * 64 + cc * 8);
        }
        // stage W: 256 rows x 8 x 16B x 2 planes = 4096 uint4
#pragma unroll
        for (int i = 0; i < 8; i++) {
            int idx = t + i * 512;
            int cc  = idx & 7;
            int ro  = (idx >> 3) & 255;
            int pl  = idx >> 11;
            const __nv_bfloat16* src = pl ? wbl : wbh;
            __nv_bfloat16* dstp = pl ? Wl : Wh;
            *(uint4*)(dstp + ro * 72 + cc * 8) =
                *(const uint4*)(src + (size_t)ro * 256 + kc * 64 + cc * 8);
        }
        __syncthreads();

#pragma unroll
        for (int k0 = 0; k0 < 4; k0++) {
            uint32_t ah[2][4], al[2][4];
#pragma unroll
            for (int s = 0; s < 2; s++) {
                int row = wm * 32 + s * 16 + g;
                int off = row * 36 + k0 * 8 + q;
                ah[s][0] = Ah32[off];
                ah[s][1] = Ah32[off + 8 * 36];
                ah[s][2] = Ah32[off + 4];
                ah[s][3] = Ah32[off + 8 * 36 + 4];
                al[s][0] = Al32[off];
                al[s][1] = Al32[off + 8 * 36];
                al[s][2] = Al32[off + 4];
                al[s][3] = Al32[off + 8 * 36 + 4];
            }
#pragma unroll
            for (int j = 0; j < 8; j++) {
                int woff = (wn * 64 + j * 8 + g) * 36 + k0 * 8 + q;
                uint32_t wh0 = Wh32[woff], wh1 = Wh32[woff + 4];
                uint32_t wl0 = Wl32[woff], wl1 = Wl32[woff + 4];
#pragma unroll
                for (int s = 0; s < 2; s++) {
                    mma_bf16(acc[s][j], ah[s], wh0, wh1);
                    mma_bf16(acc[s][j], ah[s], wl0, wl1);
                    mma_bf16(acc[s][j], al[s], wh0, wh1);
                }
            }
        }
        __syncthreads();
    }

    // epilogue: direct float2 stores (rows contiguous in C -> 32B/quad runs)
#pragma unroll
    for (int s = 0; s < 2; s++) {
        int m = m0 + wm * 32 + s * 16 + g;
#pragma unroll
        for (int j = 0; j < 8; j++) {
            int n = wn * 64 + j * 8 + 2 * q;
            float b0 = s_b[n], b1 = s_b[n + 1];
            float2 v0 = make_float2(acc[s][j][0] + b0, acc[s][j][1] + b1);
            float2 v1 = make_float2(acc[s][j][2] + b0, acc[s][j][3] + b1);
            *(float2*)(C + (size_t)m * 256 + n)       = v0;
            *(float2*)(C + (size_t)(m + 8) * 256 + n) = v1;
        }
    }
}

// ---------------------------------------------------------------------------
// 3) attention (both stages)
// ---------------------------------------------------------------------------
template <bool CROSS>
__global__ __launch_bounds__(256) void k_attn() {
    __shared__ float Qs[64][33];
    __shared__ float Ks[64][32];
    __shared__ float Vs[64][32];
    __shared__ float Ss[64][65];

    const float scale = 0.17677669529663687f;
    int blk = blockIdx.x;
    int t   = threadIdx.x;
    size_t obase = (size_t)blk * 2048;

    if (!CROSS) {
        for (int idx = t; idx < 2048; idx += 256) {
            int r = idx >> 5, d = idx & 31;
            size_t a = obase + idx;
            Qs[r][d] = g_q[a] * scale;
            Ks[r][d] = g_k[a];
            Vs[r][d] = g_v[a];
        }
    } else {
        int bh = blk >> 6, pp = blk & 63;
        size_t qb = (size_t)bh * 131072 + (size_t)pp * 32;
        for (int idx = t; idx < 2048; idx += 256) {
            int r = idx >> 5, d = idx & 31;
            size_t a = qb + (size_t)r * 2048 + d;
            Qs[r][d] = g_q[a] * scale;
            Ks[r][d] = g_k[a];
            Vs[r][d] = g_v[a];
        }
    }
    __syncthreads();

    int i  = t & 63;
    int j0 = (t >> 6) * 16;
    {
        float acc[16];
#pragma unroll
        for (int jj = 0; jj < 16; jj++) acc[jj] = 0.f;
        for (int d = 0; d < 32; d++) {
            float qv = Qs[i][d];
#pragma unroll
            for (int jj = 0; jj < 16; jj++) acc[jj] += qv * Ks[j0 + jj][d];
        }
#pragma unroll
        for (int jj = 0; jj < 16; jj++) Ss[i][j0 + jj] = acc[jj];
    }
    __syncthreads();

    {
        int r = t >> 2, q = t & 3;
        float mx = -1e30f;
        float ev[16];
#pragma unroll
        for (int c = 0; c < 16; c++) mx = fmaxf(mx, Ss[r][q * 16 + c]);
        mx = fmaxf(mx, __shfl_xor_sync(0xffffffffu, mx, 1));
        mx = fmaxf(mx, __shfl_xor_sync(0xffffffffu, mx, 2));
        float sum = 0.f;
#pragma unroll
        for (int c = 0; c < 16; c++) {
            ev[c] = __expf(Ss[r][q * 16 + c] - mx);
            sum += ev[c];
        }
        sum += __shfl_xor_sync(0xffffffffu, sum, 1);
        sum += __shfl_xor_sync(0xffffffffu, sum, 2);
        float inv = 1.0f / sum;
#pragma unroll
        for (int c = 0; c < 16; c++) Ss[r][q * 16 + c] = ev[c] * inv;
    }
    __syncthreads();

    {
        int d0 = (t >> 6) * 8;
        float oacc[8];
#pragma unroll
        for (int dd = 0; dd < 8; dd++) oacc[dd] = 0.f;
        for (int j = 0; j < 64; j++) {
            float p = Ss[i][j];
#pragma unroll
            for (int dd = 0; dd < 8; dd++) oacc[dd] += p * Vs[j][d0 + dd];
        }
#pragma unroll
        for (int dd = 0; dd < 8; dd++) Qs[i][d0 + dd] = oacc[dd];
    }
    __syncthreads();
    for (int idx = t; idx < 2048; idx += 256) {
        int r = idx >> 5, d = idx & 31;
        g_attn[obase + idx] = Qs[r][d];
    }
}

// ---------------------------------------------------------------------------
// 4a) Fused LN + sigmoid-gate + fold, INSIDE branch
// ---------------------------------------------------------------------------
__global__ __launch_bounds__(256) void k_ln_gate_inside(const float* __restrict__ x,
                                                        const float* __restrict__ lg,
                                                        const float* __restrict__ lb) {
    __shared__ float s[32][257];
    __shared__ float m_s[32], i_s[32];

    int blk  = blockIdx.x;
    int half = blk & 1;
    int n    = (blk >> 1) & 63;
    int b    = blk >> 7;
    int t    = threadIdx.x;
    int pp0  = half * 32;

    size_t base = ((size_t)((b * 64 + n) * 64 + pp0)) * 256;
#pragma unroll
    for (int i = 0; i < 32; i++) {
        int idx = t + i * 256;
        s[idx >> 8][idx & 255] = g_proj[base + idx];
    }
    __syncthreads();

    {
        int row = t >> 3, q = t & 7;
        float sum = 0.f, sum2 = 0.f;
#pragma unroll
        for (int i = 0; i < 32; i++) {
            float v = s[row][q + 8 * i];
            sum += v; sum2 += v * v;
        }
#pragma unroll
        for (int o = 1; o < 8; o <<= 1) {
            sum  += __shfl_xor_sync(0xffffffffu, sum, o);
            sum2 += __shfl_xor_sync(0xffffffffu, sum2, o);
        }
        if (q == 0) {
            float mean = sum * (1.0f / 256.0f);
            float var  = sum2 * (1.0f / 256.0f) - mean * mean;
            m_s[row] = mean;
            i_s[row] = rsqrtf(var + 1e-5f);
        }
    }
    __syncthreads();

    int h3  = t & 7;
    int wl  = (t >> 3) & 3;
    int cq8 = t >> 5;
    int row = wl * 8 + h3;
    int w   = ((n >> 3) << 3) + half * 4 + wl;
    int h   = ((n & 7) << 3) + h3;
    float mean = m_s[row], inv = i_s[row];
    size_t pix = ((size_t)w << 6) | h;
#pragma unroll
    for (int c0 = 0; c0 < 256; c0 += 8) {
        int c = c0 + cq8;
        float v = (s[row][c] - mean) * inv * lg[c] + lb[c];
        float xv = x[(((size_t)(b * 256 + c)) << 12) + pix];
        g_cat[(((size_t)(b * 512 + c)) << 12) + pix] = xv * sigm(v);
    }
}

// ---------------------------------------------------------------------------
// 4b) Fused LN + sigmoid-gate + fold, REGION branch
// ---------------------------------------------------------------------------
__global__ __launch_bounds__(256) void k_ln_gate_region(const float* __restrict__ x,
                                                        const float* __restrict__ lg,
                                                        const float* __restrict__ lb) {
    __shared__ float s[32][264];
    __shared__ float m_s[32], i_s[32];

    int blk  = blockIdx.x;
    int half = blk & 1;
    int pp2  = (blk >> 1) & 63;
    int b    = blk >> 7;
    int t    = threadIdx.x;
    int n2_0 = half * 32;

    size_t base = ((size_t)((b * 64 + pp2) * 64 + n2_0)) * 256;
#pragma unroll
    for (int i = 0; i < 32; i++) {
        int idx = t + i * 256;
        s[idx >> 8][idx & 255] = g_proj[base + idx];
    }
    __syncthreads();

    {
        int row = t >> 3, q = t & 7;
        float sum = 0.f, sum2 = 0.f;
#pragma unroll
        for (int i = 0; i < 32; i++) {
            float v = s[row][q + 8 * i];
            sum += v; sum2 += v * v;
        }
#pragma unroll
        for (int o = 1; o < 8; o <<= 1) {
            sum  += __shfl_xor_sync(0xffffffffu, sum, o);
            sum2 += __shfl_xor_sync(0xffffffffu, sum2, o);
        }
        if (q == 0) {
            float mean = sum * (1.0f / 256.0f);
            float var  = sum2 * (1.0f / 256.0f) - mean * mean;
            m_s[row] = mean;
            i_s[row] = rsqrtf(var + 1e-5f);
        }
    }
    __syncthreads();

    int ph = t & 7;
    int nl = (t >> 3) & 7;
    int pl_hi = t >> 6;
#pragma unroll
    for (int it = 0; it < 32; it++) {
        int cq  = it & 3;
        int nh  = (it >> 2) & 3;
        int ph2 = it >> 4;
        int pl  = ph2 * 4 + pl_hi;
        int row = nh * 8 + nl;
        int c2  = cq * 64 + pl * 8 + ph;
        int cf  = pp2 * 4 + cq;
        int w   = (half * 4 + nh) * 8 + pl;
        int h   = nl * 8 + ph;
        float v = (s[row][c2] - m_s[row]) * i_s[row] * lg[c2] + lb[c2];
        size_t pix = ((size_t)w << 6) | h;
        float xv = x[(((size_t)(b * 256 + cf)) << 12) + pix];
        g_cat[(((size_t)(b * 512 + 256 + cf)) << 12) + pix] = xv * sigm(v);
    }
}

// ---------------------------------------------------------------------------
// 4c) NCHW fp32 -> NHWC bf16 hi/lo split (conv1 input prep)
// ---------------------------------------------------------------------------
__global__ __launch_bounds__(256) void k_split_nhwc() {
    __shared__ float s[64][65];
    int b  = blockIdx.z;
    int c0 = blockIdx.y * 64;
    int p0 = blockIdx.x * 64;
    int t  = threadIdx.x;
#pragma unroll
    for (int i = 0; i < 16; i++) {
        int idx = i * 256 + t;
        int ch = idx >> 6, px = idx & 63;
        s[ch][px] = g_cat[(((size_t)(b * 512 + c0 + ch)) << 12) + p0 + px];
    }
    __syncthreads();
#pragma unroll
    for (int i = 0; i < 16; i++) {
        int idx = i * 256 + t;
        int px = idx >> 6, ch = idx & 63;
        float v = s[ch][px];
        __nv_bfloat16 hb = __float2bfloat16(v);
        float lv = v - __bfloat162float(hb);
        size_t o = ((size_t)(b * 4096 + p0 + px)) * 512 + c0 + ch;
        g_nh1_hi[o] = hb;
        g_nh1_lo[o] = __float2bfloat16(lv);
    }
}

// ---------------------------------------------------------------------------
// 4d) conv weight prep: fp32 OIHW -> bf16 hi/lo K-major tiles
// ---------------------------------------------------------------------------
template <int CIN>
__global__ __launch_bounds__(256) void k_prep_w(const float* __restrict__ w) {
    constexpr int KC = CIN / 64;
    int idx = blockIdx.x * 256 + threadIdx.x;     // ((tap*KC+kc)*256+co)*64+cl
    int cl = idx & 63;
    int co = (idx >> 6) & 255;
    int s  = idx >> 14;                           // tap*KC + kc
    int kc = s % KC;
    int tap = s / KC;
    float v = w[((size_t)co * CIN + kc * 64 + cl) * 9 + tap];
    __nv_bfloat16 hb = __float2bfloat16(v);
    float lv = v - __bfloat162float(hb);
    __nv_bfloat16* dst = (CIN == 512 ? g_w1s : g_w2s) + (size_t)s * 32768;
    dst[co * 64 + cl] = hb;
    dst[16384 + co * 64 + cl] = __float2bfloat16(lv);
}

// ---------------------------------------------------------------------------
// 5) mma.sync implicit-GEMM 3x3 conv + bias + BN + ReLU. (proven in R8)
// ---------------------------------------------------------------------------
template <int CIN>
__global__ __launch_bounds__(512, 1) void k_conv_mma(const float* __restrict__ cb,
                                                     const float* __restrict__ bng,
                                                     const float* __restrict__ bnb,
                                                     const float* __restrict__ bnm,
                                                     const float* __restrict__ bnv,
                                                     float* __restrict__ out) {
    constexpr int KC = CIN / 64;
    extern __shared__ __align__(16) char dsm[];
    __nv_bfloat16* Ah = (__nv_bfloat16*)dsm;        // [128][72]
    __nv_bfloat16* Al = Ah + 128 * 72;
    __nv_bfloat16* Wh = Al + 128 * 72;              // [256][72]
    __nv_bfloat16* Wl = Wh + 256 * 72;
    __shared__ float s_sc[256], s_sh[256];

    int t    = threadIdx.x;
    int b    = blockIdx.y;
    int p0   = blockIdx.x * 128;
    int lane = t & 31;
    int wid  = t >> 5;
    int wm   = wid & 3;
    int wn   = wid >> 2;
    int g    = lane >> 2;
    int q    = lane & 3;

    if (t < 256) {
        float inv = rsqrtf(bnv[t] + 1e-5f);
        float sc = bng[t] * inv;
        s_sc[t] = sc;
        s_sh[t] = (cb[t] - bnm[t]) * sc + bnb[t];
    }

    float acc[2][8][4];
#pragma unroll
    for (int s = 0; s < 2; s++)
#pragma unroll
        for (int j = 0; j < 8; j++)
#pragma unroll
            for (int r = 0; r < 4; r++) acc[s][j][r] = 0.f;

    const __nv_bfloat16* nin_hi = (CIN == 512) ? g_nh1_hi : g_nh2_hi;
    const __nv_bfloat16* nin_lo = (CIN == 512) ? g_nh1_lo : g_nh2_lo;
    const __nv_bfloat16* wsrc   = (CIN == 512) ? g_w1s : g_w2s;

    const uint32_t* Ah32 = (const uint32_t*)Ah;
    const uint32_t* Al32 = (const uint32_t*)Al;
    const uint32_t* Wh32 = (const uint32_t*)Wh;
    const uint32_t* Wl32 = (const uint32_t*)Wl;

    int y0 = p0 >> 6;

    for (int tap = 0; tap < 9; tap++) {
        int dy = tap / 3 - 1;
        int dx = tap % 3 - 1;
        for (int kc = 0; kc < KC; kc++) {
#pragma unroll
            for (int i = 0; i < 4; i++) {
                int idx = t + i * 512;
                int cc  = idx & 7;
                int r   = (idx >> 3) & 127;
                int pl  = idx >> 10;
                int y = y0 + (r >> 6) + dy;
                int x = (r & 63) + dx;
                uint4 val = make_uint4(0, 0, 0, 0);
                if (y >= 0 && y < 64 && x >= 0 && x < 64) {
                    const __nv_bfloat16* src = pl ? nin_lo : nin_hi;
                    val = *(const uint4*)(src + ((size_t)(b * 4096 + y * 64 + x)) * CIN
                                          + kc * 64 + cc * 8);
                }
                __nv_bfloat16* dstp = pl ? Al : Ah;
                *(uint4*)(dstp + r * 72 + cc * 8) = val;
            }
            {
                const __nv_bfloat16* wbase = wsrc + (size_t)(tap * KC + kc) * 32768;
#pragma unroll
                for (int i = 0; i < 8; i++) {
                    int idx = t + i * 512;
                    int cc  = idx & 7;
                    int co  = (idx >> 3) & 255;
                    int pl  = idx >> 11;
                    __nv_bfloat16* dstp = pl ? Wl : Wh;
                    *(uint4*)(dstp + co * 72 + cc * 8) =
                        *(const uint4*)(wbase + pl * 16384 + co * 64 + cc * 8);
                }
            }
            __syncthreads();

#pragma unroll
            for (int k0 = 0; k0 < 4; k0++) {
                uint32_t ah[2][4], al[2][4];
#pragma unroll
                for (int s = 0; s < 2; s++) {
                    int row = wm * 32 + s * 16 + g;
                    int off = row * 36 + k0 * 8 + q;
                    ah[s][0] = Ah32[off];
                    ah[s][1] = Ah32[off + 8 * 36];
                    ah[s][2] = Ah32[off + 4];
                    ah[s][3] = Ah32[off + 8 * 36 + 4];
                    al[s][0] = Al32[off];
                    al[s][1] = Al32[off + 8 * 36];
                    al[s][2] = Al32[off + 4];
                    al[s][3] = Al32[off + 8 * 36 + 4];
                }
#pragma unroll
                for (int j = 0; j < 8; j++) {
                    int woff = (wn * 64 + j * 8 + g) * 36 + k0 * 8 + q;
                    uint32_t wh0 = Wh32[woff], wh1 = Wh32[woff + 4];
                    uint32_t wl0 = Wl32[woff], wl1 = Wl32[woff + 4];
#pragma unroll
                    for (int s = 0; s < 2; s++) {
                        mma_bf16(acc[s][j], ah[s], wh0, wh1);
                        mma_bf16(acc[s][j], ah[s], wl0, wl1);
                        mma_bf16(acc[s][j], al[s], wh0, wh1);
                    }
                }
            }
            __syncthreads();
        }
    }

#pragma unroll
    for (int s = 0; s < 2; s++) {
        int m = p0 + wm * 32 + s * 16 + g;
#pragma unroll
        for (int j = 0; j < 8; j++) {
            int n = wn * 64 + j * 8 + 2 * q;
            float v0 = fmaxf(acc[s][j][0] * s_sc[n]     + s_sh[n],     0.f);
            float v1 = fmaxf(acc[s][j][1] * s_sc[n + 1] + s_sh[n + 1], 0.f);
            float v2 = fmaxf(acc[s][j][2] * s_sc[n]     + s_sh[n],     0.f);
            float v3 = fmaxf(acc[s][j][3] * s_sc[n + 1] + s_sh[n + 1], 0.f);
            if (CIN == 512) {
                size_t r0 = ((size_t)(b * 4096 + m)) * 256 + n;
                size_t r1 = ((size_t)(b * 4096 + m + 8)) * 256 + n;
                *(uint32_t*)(g_nh2_hi + r0) = packh2(v0, v1);
                *(uint32_t*)(g_nh2_lo + r0) = packl2(v0, v1);
                *(uint32_t*)(g_nh2_hi + r1) = packh2(v2, v3);
                *(uint32_t*)(g_nh2_lo + r1) = packl2(v2, v3);
            } else {
                out[(((size_t)(b * 256 + n)) << 12) + m]         = v0;
                out[(((size_t)(b * 256 + n + 1)) << 12) + m]     = v1;
                out[(((size_t)(b * 256 + n)) << 12) + m + 8]     = v2;
                out[(((size_t)(b * 256 + n + 1)) << 12) + m + 8] = v3;
            }
        }
    }
}

// ---------------------------------------------------------------------------
// launch: NO __device__ symbols in any argument list (only harness pointers
// and selector ints).
// ---------------------------------------------------------------------------
extern "C" void kernel_launch(void* const* d_in, const int* in_sizes, int n_in,
                              void* d_out, int out_size) {
    (void)in_sizes; (void)n_in; (void)out_size;
    const float* x     = (const float*)d_in[0];
    const float* Wq    = (const float*)d_in[1];
    const float* Wk    = (const float*)d_in[2];
    const float* Wv    = (const float*)d_in[3];
    const float* Wpi   = (const float*)d_in[4];
    const float* bpi   = (const float*)d_in[5];
    const float* lni_g = (const float*)d_in[6];
    const float* lni_b = (const float*)d_in[7];
    const float* Wpr   = (const float*)d_in[8];
    const float* bpr   = (const float*)d_in[9];
    const float* lnr_g = (const float*)d_in[10];
    const float* lnr_b = (const float*)d_in[11];
    const float* cw1   = (const float*)d_in[12];
    const float* cb1   = (const float*)d_in[13];
    const float* bn1_g = (const float*)d_in[14];
    const float* bn1_b = (const float*)d_in[15];
    const float* bn1_m = (const float*)d_in[16];
    const float* bn1_v = (const float*)d_in[17];
    const float* cw2   = (const float*)d_in[18];
    const float* cb2   = (const float*)d_in[19];
    const float* bn2_g = (const float*)d_in[20];
    const float* bn2_b = (const float*)d_in[21];
    const float* bn2_m = (const float*)d_in[22];
    const float* bn2_v = (const float*)d_in[23];
    float* out = (float*)d_out;

    const int NB = NELEM / 256;
    const int GEMM_SMEM = (2 * 128 * 72 + 2 * 256 * 72) * 2;   // 110592 B

    cudaFuncSetAttribute(k_conv_mma<512>, cudaFuncAttributeMaxDynamicSharedMemorySize, GEMM_SMEM);
    cudaFuncSetAttribute(k_conv_mma<256>, cudaFuncAttributeMaxDynamicSharedMemorySize, GEMM_SMEM);
    cudaFuncSetAttribute(k_gemm_mma<0>, cudaFuncAttributeMaxDynamicSharedMemorySize, GEMM_SMEM);
    cudaFuncSetAttribute(k_gemm_mma<1>, cudaFuncAttributeMaxDynamicSharedMemorySize, GEMM_SMEM);

    // weight prep (independent of data path)
    k_prep_w<512><<<(9 * 8 * 16384) / 256, 256>>>(cw1);
    k_prep_w<256><<<(9 * 4 * 16384) / 256, 256>>>(cw2);
    k_split_w<<<64, 256>>>(Wq, 0);
    k_split_w<<<64, 256>>>(Wk, 1);
    k_split_w<<<64, 256>>>(Wv, 2);
    k_split_w<<<64, 256>>>(Wpi, 3);
    k_split_w<<<64, 256>>>(Wpr, 4);

    k_unfold<<<NB, 256>>>(x);
    k_split_a<<<NELEM / 1024, 256>>>(0);
    k_gemm_mma<0><<<512, 512, GEMM_SMEM>>>(0, 0, nullptr);
    k_gemm_mma<0><<<512, 512, GEMM_SMEM>>>(1, 1, nullptr);
    k_gemm_mma<0><<<512, 512, GEMM_SMEM>>>(2, 2, nullptr);

    k_attn<false><<<8192, 256>>>();
    k_split_a<<<NELEM / 1024, 256>>>(1);
    k_gemm_mma<1><<<512, 512, GEMM_SMEM>>>(3, 3, bpi);
    k_ln_gate_inside<<<2048, 256>>>(x, lni_g, lni_b);

    k_attn<true><<<8192, 256>>>();
    k_split_a<<<NELEM / 1024, 256>>>(1);
    k_gemm_mma<1><<<512, 512, GEMM_SMEM>>>(4, 3, bpr);
    k_ln_gate_region<<<2048, 256>>>(x, lnr_g, lnr_b);

    k_split_nhwc<<<dim3(64, 8, 16), 256>>>();

    k_conv_mma<512><<<dim3(32, 16), 512, GEMM_SMEM>>>(cb1, bn1_g, bn1_b, bn1_m, bn1_v, nullptr);
    k_conv_mma<256><<<dim3(32, 16), 512, GEMM_SMEM>>>(cb2, bn2_g, bn2_b, bn2_m, bn2_v, out);
}